// round 1
// baseline (speedup 1.0000x reference)
#include <cuda_runtime.h>

// B=2, S=2048, D=768, H=12, DH=64
#define SB 2
#define SS 2048
#define SD 768
#define SH 12
#define SDH 64

// Scratch (static device globals — no allocations allowed)
__device__ float g_q[SB*SH*SS*SDH];    // [b][h][s][dh]
__device__ float g_k[SB*SH*SS*SDH];
__device__ float g_v[SB*SH*SS*SDH];
__device__ float g_att[SB*SS*SD];      // [b][s][d]

// ---------------------------------------------------------------------------
// GEMM: C[m,n] = sum_k A[m,k] * W[n,k] + bias[n]   (A: [4096,768], W: [768,768])
// MODE 1/2/3: A = input param (q/k/v), output scattered to g_q/g_k/g_v [b,h,s,dh]
// MODE 0:     A = g_att, output plain [m,768] to param `out` (final projection)
// 64x64 tile, BK=16, 256 threads, 4x4 micro-tile per thread.
// Smem stored k-major with XOR swizzle: element (k, c) at [k][c ^ (k & 12)].
// ---------------------------------------------------------------------------
template<int MODE>
__global__ __launch_bounds__(256) void gemm_k768(
    const float* __restrict__ A,
    const float* __restrict__ W,
    const float* __restrict__ bias,
    float* __restrict__ out)
{
    __shared__ float As[16][64];
    __shared__ float Ws[16][64];

    const int tid = threadIdx.x;
    const int tx  = tid & 15;
    const int ty  = tid >> 4;
    const int m0  = blockIdx.x << 6;
    const int n0  = blockIdx.y << 6;

    const float* Ap = (MODE == 0) ? g_att : A;

    // load roles: each thread loads one float4 of A and one of W per k-step
    const int lr = tid >> 2;          // 0..63 (row within tile)
    const int lk = (tid & 3) << 2;    // 0,4,8,12 (k offset)
    const float* Ag = Ap + (m0 + lr) * 768 + lk;
    const float* Wg = W  + (n0 + lr) * 768 + lk;

    float acc[4][4] = {};

    for (int k0 = 0; k0 < 768; k0 += 16) {
        float4 a4 = *(const float4*)(Ag + k0);
        float4 w4 = *(const float4*)(Wg + k0);
        const int sc = lr ^ lk;       // (lk+j)&12 == lk for j<4
        As[lk+0][sc] = a4.x;  As[lk+1][sc] = a4.y;
        As[lk+2][sc] = a4.z;  As[lk+3][sc] = a4.w;
        Ws[lk+0][sc] = w4.x;  Ws[lk+1][sc] = w4.y;
        Ws[lk+2][sc] = w4.z;  Ws[lk+3][sc] = w4.w;
        __syncthreads();

        #pragma unroll
        for (int kk = 0; kk < 16; ++kk) {
            const int sz = kk & 12;
            float4 av = *(const float4*)&As[kk][(ty << 2) ^ sz];
            float4 wv = *(const float4*)&Ws[kk][(tx << 2) ^ sz];
            float a_[4] = {av.x, av.y, av.z, av.w};
            float w_[4] = {wv.x, wv.y, wv.z, wv.w};
            #pragma unroll
            for (int i = 0; i < 4; ++i)
                #pragma unroll
                for (int j = 0; j < 4; ++j)
                    acc[i][j] += a_[i] * w_[j];
        }
        __syncthreads();
    }

    float4 bv = *(const float4*)&bias[n0 + (tx << 2)];
    #pragma unroll
    for (int i = 0; i < 4; ++i) {
        const int m = m0 + (ty << 2) + i;
        float4 r;
        r.x = acc[i][0] + bv.x;
        r.y = acc[i][1] + bv.y;
        r.z = acc[i][2] + bv.z;
        r.w = acc[i][3] + bv.w;
        if (MODE != 0) {
            float* dst = (MODE == 1) ? g_q : (MODE == 2) ? g_k : g_v;
            const int b = m >> 11;          // m / 2048
            const int s = m & 2047;
            const int h = n0 >> 6;
            // [b][h][s][dh], dh = 4*tx .. 4*tx+3
            *(float4*)&dst[(((b * 12 + h) << 11) + s) * 64 + (tx << 2)] = r;
        } else {
            *(float4*)&out[m * 768 + n0 + (tx << 2)] = r;
        }
    }
}

// ---------------------------------------------------------------------------
// Flash attention, fp32. Per block: one (b,h) and 64 q-rows; loop 64-key tiles.
// softmax((Q Kt + mask) / 8) @ V with online softmax.
// Smem: Qt [d][i] swizzled, KP [d][j] swizzled (reused as Pt [j][i] swizzled),
// Vs [j][c] natural. Exactly 48KB.
// ---------------------------------------------------------------------------
__global__ __launch_bounds__(256) void flash_attn(const float* __restrict__ mask)
{
    __shared__ float Qt[64][64];
    __shared__ float KP[64][64];
    __shared__ float Vs[64][64];

    const int tid = threadIdx.x;
    const int tx  = tid & 15;
    const int ty  = tid >> 4;
    const int q0  = blockIdx.x << 6;
    const int bh  = blockIdx.y;                  // b*12 + h
    const size_t base = (size_t)bh * SS * SDH;

    const int li = tid >> 4;                     // 0..15
    const int ld = (tid & 15) << 2;              // 0..60 step 4

    // Load Q tile transposed+swizzled: element (d, i) at Qt[d][i ^ (d&60)]
    #pragma unroll
    for (int r = 0; r < 4; ++r) {
        const int i = (r << 4) + li;
        float4 qv = *(const float4*)&g_q[base + (size_t)(q0 + i) * 64 + ld];
        const int c = i ^ ld;                    // (ld+j)&60 == ld
        Qt[ld+0][c] = qv.x;  Qt[ld+1][c] = qv.y;
        Qt[ld+2][c] = qv.z;  Qt[ld+3][c] = qv.w;
    }

    float m_i[4], l_i[4], o[4][4];
    #pragma unroll
    for (int i = 0; i < 4; ++i) {
        m_i[i] = -1e30f; l_i[i] = 0.f;
        #pragma unroll
        for (int j = 0; j < 4; ++j) o[i][j] = 0.f;
    }

    for (int k0 = 0; k0 < SS; k0 += 64) {
        __syncthreads();   // previous iteration done reading KP/Vs
        #pragma unroll
        for (int r = 0; r < 4; ++r) {
            const int j = (r << 4) + li;
            float4 kv = *(const float4*)&g_k[base + (size_t)(k0 + j) * 64 + ld];
            float4 vv = *(const float4*)&g_v[base + (size_t)(k0 + j) * 64 + ld];
            const int c = j ^ ld;
            KP[ld+0][c] = kv.x;  KP[ld+1][c] = kv.y;
            KP[ld+2][c] = kv.z;  KP[ld+3][c] = kv.w;
            *(float4*)&Vs[j][ld] = vv;
        }
        __syncthreads();

        // scores S = Q @ K^T  (64x64, 4x4 per thread)
        float s[4][4] = {};
        #pragma unroll 16
        for (int d = 0; d < 64; ++d) {
            const int sz = d & 60;
            float4 qv = *(const float4*)&Qt[d][(ty << 2) ^ sz];
            float4 kv = *(const float4*)&KP[d][(tx << 2) ^ sz];
            float q_[4] = {qv.x, qv.y, qv.z, qv.w};
            float k_[4] = {kv.x, kv.y, kv.z, kv.w};
            #pragma unroll
            for (int i = 0; i < 4; ++i)
                #pragma unroll
                for (int j = 0; j < 4; ++j)
                    s[i][j] += q_[i] * k_[j];
        }

        // mask, scale 1/sqrt(64), online softmax (row groups share ty; 16-lane shfl)
        float p[4][4];
        float al[4];
        #pragma unroll
        for (int i = 0; i < 4; ++i) {
            float4 mk = *(const float4*)&mask[(size_t)(q0 + (ty << 2) + i) * SS + k0 + (tx << 2)];
            float v0 = (s[i][0] + mk.x) * 0.125f;
            float v1 = (s[i][1] + mk.y) * 0.125f;
            float v2 = (s[i][2] + mk.z) * 0.125f;
            float v3 = (s[i][3] + mk.w) * 0.125f;
            float rmax = fmaxf(fmaxf(v0, v1), fmaxf(v2, v3));
            #pragma unroll
            for (int off = 8; off > 0; off >>= 1)
                rmax = fmaxf(rmax, __shfl_xor_sync(0xffffffffu, rmax, off, 16));
            const float mn = fmaxf(m_i[i], rmax);
            const float a  = __expf(m_i[i] - mn);
            m_i[i] = mn;
            float p0 = __expf(v0 - mn), p1 = __expf(v1 - mn);
            float p2 = __expf(v2 - mn), p3 = __expf(v3 - mn);
            float rs = p0 + p1 + p2 + p3;
            #pragma unroll
            for (int off = 8; off > 0; off >>= 1)
                rs += __shfl_xor_sync(0xffffffffu, rs, off, 16);
            l_i[i] = l_i[i] * a + rs;
            al[i] = a;
            p[i][0] = p0; p[i][1] = p1; p[i][2] = p2; p[i][3] = p3;
        }
        #pragma unroll
        for (int i = 0; i < 4; ++i)
            #pragma unroll
            for (int j = 0; j < 4; ++j)
                o[i][j] *= al[i];

        __syncthreads();   // all threads done reading KP as K
        // write P transposed+swizzled into KP: element (j, i) at KP[j][i ^ (j&60)]
        #pragma unroll
        for (int jj = 0; jj < 4; ++jj) {
            const int j = (tx << 2) + jj;        // j&60 == tx<<2
            const int c = (ty << 2) ^ (tx << 2);
            float4 pv4 = make_float4(p[0][jj], p[1][jj], p[2][jj], p[3][jj]);
            *(float4*)&KP[j][c] = pv4;
        }
        __syncthreads();

        // O += P @ V  (64x64 @ 64x64)
        #pragma unroll 16
        for (int j = 0; j < 64; ++j) {
            const int sz = j & 60;
            float4 pv = *(const float4*)&KP[j][(ty << 2) ^ sz];
            float4 vv = *(const float4*)&Vs[j][tx << 2];
            float p_[4] = {pv.x, pv.y, pv.z, pv.w};
            float v_[4] = {vv.x, vv.y, vv.z, vv.w};
            #pragma unroll
            for (int i = 0; i < 4; ++i)
                #pragma unroll
                for (int cc = 0; cc < 4; ++cc)
                    o[i][cc] += p_[i] * v_[cc];
        }
    }

    // epilogue: normalize and write to g_att [b][s][h*64+dh]
    const int b = bh / 12;
    const int h = bh % 12;
    #pragma unroll
    for (int i = 0; i < 4; ++i) {
        const float inv = 1.0f / l_i[i];
        float4 r = make_float4(o[i][0] * inv, o[i][1] * inv, o[i][2] * inv, o[i][3] * inv);
        const int srow = q0 + (ty << 2) + i;
        *(float4*)&g_att[((size_t)b * SS + srow) * SD + h * 64 + (tx << 2)] = r;
    }
}

// ---------------------------------------------------------------------------
extern "C" void kernel_launch(void* const* d_in, const int* in_sizes, int n_in,
                              void* d_out, int out_size)
{
    const float* q    = (const float*)d_in[0];
    const float* k    = (const float*)d_in[1];
    const float* v    = (const float*)d_in[2];
    const float* mask = (const float*)d_in[3];
    const float* Wq   = (const float*)d_in[4];
    const float* bq   = (const float*)d_in[5];
    const float* Wk   = (const float*)d_in[6];
    const float* bk   = (const float*)d_in[7];
    const float* Wv   = (const float*)d_in[8];
    const float* bv   = (const float*)d_in[9];
    const float* Wo   = (const float*)d_in[10];
    const float* bo   = (const float*)d_in[11];
    float* out = (float*)d_out;

    (void)in_sizes; (void)n_in; (void)out_size;

    dim3 gemm_grid(4096 / 64, 768 / 64);   // 64 x 12
    dim3 flash_grid(SS / 64, SB * SH);     // 32 x 24

    gemm_k768<1><<<gemm_grid, 256>>>(q, Wq, bq, nullptr);
    gemm_k768<2><<<gemm_grid, 256>>>(k, Wk, bk, nullptr);
    gemm_k768<3><<<gemm_grid, 256>>>(v, Wv, bv, nullptr);
    flash_attn<<<flash_grid, 256>>>(mask);
    gemm_k768<0><<<gemm_grid, 256>>>(nullptr, Wo, bo, out);
}

// round 3
// speedup vs baseline: 1.3268x; 1.3268x over previous
#include <cuda_runtime.h>
#include <cuda_bf16.h>
#include <cstdint>

// B=2, S=2048, D=768, H=12, DH=64
#define SB 2
#define SS 2048
#define SD 768
#define SH 12
#define SDH 64

// ---------------------------------------------------------------------------
// Scratch (static device globals — no allocations allowed)
// ---------------------------------------------------------------------------
__device__ float g_q[SB*SH*SS*SDH];    // [b][h][s][dh] fp32 (flash inputs)
__device__ float g_k[SB*SH*SS*SDH];
__device__ float g_v[SB*SH*SS*SDH];

__device__ __nv_bfloat16 g_inh[3][4096*768];   // q,k,v inputs split hi
__device__ __nv_bfloat16 g_inl[3][4096*768];   // lo
__device__ __nv_bfloat16 g_wh[4][768*768];     // Wq,Wk,Wv,Wo hi
__device__ __nv_bfloat16 g_wl[4][768*768];     // lo
__device__ __nv_bfloat16 g_atth[4096*768];     // attention output split hi
__device__ __nv_bfloat16 g_attl[4096*768];     // lo

// ---------------------------------------------------------------------------
__device__ __forceinline__ uint32_t smem_u32(const void* p) {
    uint32_t a;
    asm("{ .reg .u64 t; cvta.to.shared.u64 t, %1; cvt.u32.u64 %0, t; }"
        : "=r"(a) : "l"(p));
    return a;
}

#define LDSM_X4(r0, r1, r2, r3, addr) \
    asm volatile("ldmatrix.sync.aligned.m8n8.x4.shared.b16 {%0,%1,%2,%3}, [%4];" \
        : "=r"(r0), "=r"(r1), "=r"(r2), "=r"(r3) : "r"(addr))

#define MMA_BF16(d, a, b) \
    asm volatile("mma.sync.aligned.m16n8k16.row.col.f32.bf16.bf16.f32 " \
        "{%0,%1,%2,%3}, {%4,%5,%6,%7}, {%8,%9}, {%0,%1,%2,%3};" \
        : "+f"((d)[0]), "+f"((d)[1]), "+f"((d)[2]), "+f"((d)[3]) \
        : "r"((a)[0]), "r"((a)[1]), "r"((a)[2]), "r"((a)[3]), \
          "r"((b)[0]), "r"((b)[1]))

// ---------------------------------------------------------------------------
// fp32 -> bf16 (hi, lo) split.  kind 0: inputs; kind 1: weights.
// ---------------------------------------------------------------------------
__global__ __launch_bounds__(256) void split_bf16(const float* __restrict__ x,
                                                  int kind, int idx) {
    const int i = (blockIdx.x * 256 + threadIdx.x) * 4;
    __nv_bfloat16* hi;
    __nv_bfloat16* lo;
    if (kind == 0) { hi = g_inh[idx]; lo = g_inl[idx]; }
    else           { hi = g_wh[idx];  lo = g_wl[idx];  }
    float4 v = *(const float4*)(x + i);
    __nv_bfloat16 h0 = __float2bfloat16(v.x);
    __nv_bfloat16 h1 = __float2bfloat16(v.y);
    __nv_bfloat16 h2 = __float2bfloat16(v.z);
    __nv_bfloat16 h3 = __float2bfloat16(v.w);
    __nv_bfloat16 l0 = __float2bfloat16(v.x - __bfloat162float(h0));
    __nv_bfloat16 l1 = __float2bfloat16(v.y - __bfloat162float(h1));
    __nv_bfloat16 l2 = __float2bfloat16(v.z - __bfloat162float(h2));
    __nv_bfloat16 l3 = __float2bfloat16(v.w - __bfloat162float(h3));
    *(__nv_bfloat162*)(hi + i)     = __nv_bfloat162(h0, h1);
    *(__nv_bfloat162*)(hi + i + 2) = __nv_bfloat162(h2, h3);
    *(__nv_bfloat162*)(lo + i)     = __nv_bfloat162(l0, l1);
    *(__nv_bfloat162*)(lo + i + 2) = __nv_bfloat162(l2, l3);
}

// ---------------------------------------------------------------------------
// HMMA GEMM: C[m,n] = sum_k A[m,k] * W[n,k] + bias[n]
// 2-term bf16 split: C = Ah*Bh + Ah*Bl + Al*Bh  (fp32 accum in registers)
// CTA 128x128, 512 threads (16 warps of 32x32), K chunks of 64, reg-prefetch.
// Smem per chunk: Ah/Al/Bh/Bl each [128 rows][64 k] bf16, XOR-swizzled 128B rows.
// MODE 1/2/3: A = g_inh/l[MODE-1], scatter to g_q/g_k/g_v [b,h,s,dh].
// MODE 0:     A = g_atth/l, W = Wo, plain store to `out`.
// ---------------------------------------------------------------------------
#define SM_BIAS 0
#define SM_AH   1024
#define SM_AL   (1024 + 16384)
#define SM_BH   (1024 + 32768)
#define SM_BL   (1024 + 49152)
#define SM_TOT  (1024 + 65536)

template<int MODE>
__global__ __launch_bounds__(512, 1) void gemm_tc(const float* __restrict__ bias,
                                                  float* __restrict__ out) {
    extern __shared__ __align__(1024) char smem[];
    const int tid = threadIdx.x;
    const int wid = tid >> 5;
    const int lid = tid & 31;
    const int m0 = blockIdx.x << 7;
    const int n0 = blockIdx.y << 7;
    const uint32_t sb = smem_u32(smem);

    const int widx = (MODE == 0) ? 3 : (MODE - 1);
    const __nv_bfloat16* Ah = (MODE == 0) ? g_atth : g_inh[widx];
    const __nv_bfloat16* Al = (MODE == 0) ? g_attl : g_inl[widx];
    const __nv_bfloat16* Bh = g_wh[widx];
    const __nv_bfloat16* Bl = g_wl[widx];

    if (tid < 32)
        ((float4*)(smem + SM_BIAS))[tid] = ((const float4*)(bias + n0))[tid];

    // global load indices: 2 x 16B units per matrix per thread
    const int i0 = tid, i1 = tid + 512;        // 0..1023 each
    const int r0_ = i0 >> 3, u0 = i0 & 7;      // row 0..127, 16B unit 0..7
    const int r1_ = i1 >> 3, u1 = i1 & 7;
    const uint32_t so0 = (uint32_t)(r0_ * 128 + ((u0 * 16) ^ ((r0_ & 7) << 4)));
    const uint32_t so1 = (uint32_t)(r1_ * 128 + ((u1 * 16) ^ ((r1_ & 7) << 4)));

    float acc[2][4][4];
    #pragma unroll
    for (int mt = 0; mt < 2; ++mt)
        #pragma unroll
        for (int nt = 0; nt < 4; ++nt)
            #pragma unroll
            for (int e = 0; e < 4; ++e) acc[mt][nt][e] = 0.f;

    const int wm = (wid >> 2) << 5;   // warp m offset 0/32/64/96
    const int wn = (wid & 3) << 5;    // warp n offset

    // ldmatrix lane addressing (within-warp)
    const int lq = lid >> 3;          // matrix index 0..3
    const int lr = lid & 7;           // row within matrix

    uint4 pa0, pa1, pl0, pl1, pb0, pb1, pq0, pq1;
    {   // prefetch chunk 0
        const int ka = 0;
        pa0 = *(const uint4*)(Ah + (size_t)(m0 + r0_) * 768 + ka + u0 * 8);
        pa1 = *(const uint4*)(Ah + (size_t)(m0 + r1_) * 768 + ka + u1 * 8);
        pl0 = *(const uint4*)(Al + (size_t)(m0 + r0_) * 768 + ka + u0 * 8);
        pl1 = *(const uint4*)(Al + (size_t)(m0 + r1_) * 768 + ka + u1 * 8);
        pb0 = *(const uint4*)(Bh + (size_t)(n0 + r0_) * 768 + ka + u0 * 8);
        pb1 = *(const uint4*)(Bh + (size_t)(n0 + r1_) * 768 + ka + u1 * 8);
        pq0 = *(const uint4*)(Bl + (size_t)(n0 + r0_) * 768 + ka + u0 * 8);
        pq1 = *(const uint4*)(Bl + (size_t)(n0 + r1_) * 768 + ka + u1 * 8);
    }

    for (int c = 0; c < 12; ++c) {
        *(uint4*)(smem + SM_AH + so0) = pa0;  *(uint4*)(smem + SM_AH + so1) = pa1;
        *(uint4*)(smem + SM_AL + so0) = pl0;  *(uint4*)(smem + SM_AL + so1) = pl1;
        *(uint4*)(smem + SM_BH + so0) = pb0;  *(uint4*)(smem + SM_BH + so1) = pb1;
        *(uint4*)(smem + SM_BL + so0) = pq0;  *(uint4*)(smem + SM_BL + so1) = pq1;
        __syncthreads();

        if (c < 11) {
            const int ka = (c + 1) << 6;
            pa0 = *(const uint4*)(Ah + (size_t)(m0 + r0_) * 768 + ka + u0 * 8);
            pa1 = *(const uint4*)(Ah + (size_t)(m0 + r1_) * 768 + ka + u1 * 8);
            pl0 = *(const uint4*)(Al + (size_t)(m0 + r0_) * 768 + ka + u0 * 8);
            pl1 = *(const uint4*)(Al + (size_t)(m0 + r1_) * 768 + ka + u1 * 8);
            pb0 = *(const uint4*)(Bh + (size_t)(n0 + r0_) * 768 + ka + u0 * 8);
            pb1 = *(const uint4*)(Bh + (size_t)(n0 + r1_) * 768 + ka + u1 * 8);
            pq0 = *(const uint4*)(Bl + (size_t)(n0 + r0_) * 768 + ka + u0 * 8);
            pq1 = *(const uint4*)(Bl + (size_t)(n0 + r1_) * 768 + ka + u1 * 8);
        }

        #pragma unroll
        for (int ks = 0; ks < 4; ++ks) {
            // A fragments (16x16 per m-tile): hi + lo
            uint32_t ah[2][4], alr[2][4];
            #pragma unroll
            for (int mt = 0; mt < 2; ++mt) {
                const int row = wm + mt * 16 + ((lq & 1) << 3) + lr;
                const int kc  = (ks << 4) + ((lq >> 1) << 3);
                const uint32_t off = (uint32_t)(row * 128 + ((kc * 2) ^ ((row & 7) << 4)));
                LDSM_X4(ah[mt][0], ah[mt][1], ah[mt][2], ah[mt][3], sb + SM_AH + off);
                LDSM_X4(alr[mt][0], alr[mt][1], alr[mt][2], alr[mt][3], sb + SM_AL + off);
            }
            // B fragments: two x4 loads cover 16 n-cols each (2 n8 frags per load)
            uint32_t bh[4][2], bl[4][2];
            #pragma unroll
            for (int half = 0; half < 2; ++half) {
                const int nrow = wn + half * 16 + ((lq >> 1) << 3) + lr;
                const int kc   = (ks << 4) + ((lq & 1) << 3);
                const uint32_t off = (uint32_t)(nrow * 128 + ((kc * 2) ^ ((nrow & 7) << 4)));
                uint32_t t0, t1, t2, t3;
                LDSM_X4(t0, t1, t2, t3, sb + SM_BH + off);
                bh[half * 2][0] = t0;     bh[half * 2][1] = t1;
                bh[half * 2 + 1][0] = t2; bh[half * 2 + 1][1] = t3;
                LDSM_X4(t0, t1, t2, t3, sb + SM_BL + off);
                bl[half * 2][0] = t0;     bl[half * 2][1] = t1;
                bl[half * 2 + 1][0] = t2; bl[half * 2 + 1][1] = t3;
            }
            #pragma unroll
            for (int mt = 0; mt < 2; ++mt)
                #pragma unroll
                for (int nt = 0; nt < 4; ++nt) {
                    MMA_BF16(acc[mt][nt], ah[mt], bh[nt]);
                    MMA_BF16(acc[mt][nt], ah[mt], bl[nt]);
                    MMA_BF16(acc[mt][nt], alr[mt], bh[nt]);
                }
        }
        __syncthreads();
    }

    // epilogue
    const int gID = lid >> 2;
    const int tc  = (lid & 3) << 1;
    const float* bs = (const float*)(smem + SM_BIAS);
    #pragma unroll
    for (int mt = 0; mt < 2; ++mt)
        #pragma unroll
        for (int nt = 0; nt < 4; ++nt) {
            const int colr = wn + nt * 8 + tc;           // 0..127 within n-block
            const float b0 = bs[colr], b1 = bs[colr + 1];
            #pragma unroll
            for (int rh = 0; rh < 2; ++rh) {             // row / row+8
                const int m = m0 + wm + mt * 16 + gID + rh * 8;
                float2 r;
                r.x = acc[mt][nt][rh * 2 + 0] + b0;
                r.y = acc[mt][nt][rh * 2 + 1] + b1;
                if (MODE != 0) {
                    float* dst = (MODE == 1) ? g_q : (MODE == 2) ? g_k : g_v;
                    const int b = m >> 11;
                    const int s = m & 2047;
                    const int head = (n0 + colr) >> 6;
                    const int dh   = (n0 + colr) & 63;
                    *(float2*)&dst[((size_t)((b * 12 + head) << 11) + s) * 64 + dh] = r;
                } else {
                    *(float2*)&out[(size_t)m * 768 + n0 + colr] = r;
                }
            }
        }
}

// ---------------------------------------------------------------------------
// Flash attention, fp32 (identical math to the 1396us-passing version).
// Epilogue writes bf16 hi/lo split for the HMMA out-projection.
// ---------------------------------------------------------------------------
__global__ __launch_bounds__(256) void flash_attn(const float* __restrict__ mask)
{
    __shared__ float Qt[64][64];
    __shared__ float KP[64][64];
    __shared__ float Vs[64][64];

    const int tid = threadIdx.x;
    const int tx  = tid & 15;
    const int ty  = tid >> 4;
    const int q0  = blockIdx.x << 6;
    const int bh  = blockIdx.y;                  // b*12 + h
    const size_t base = (size_t)bh * SS * SDH;

    const int li = tid >> 4;                     // 0..15
    const int ld = (tid & 15) << 2;              // 0..60 step 4

    #pragma unroll
    for (int r = 0; r < 4; ++r) {
        const int i = (r << 4) + li;
        float4 qv = *(const float4*)&g_q[base + (size_t)(q0 + i) * 64 + ld];
        const int c = i ^ ld;
        Qt[ld+0][c] = qv.x;  Qt[ld+1][c] = qv.y;
        Qt[ld+2][c] = qv.z;  Qt[ld+3][c] = qv.w;
    }

    float m_i[4], l_i[4], o[4][4];
    #pragma unroll
    for (int i = 0; i < 4; ++i) {
        m_i[i] = -1e30f; l_i[i] = 0.f;
        #pragma unroll
        for (int j = 0; j < 4; ++j) o[i][j] = 0.f;
    }

    for (int k0 = 0; k0 < SS; k0 += 64) {
        __syncthreads();
        #pragma unroll
        for (int r = 0; r < 4; ++r) {
            const int j = (r << 4) + li;
            float4 kv = *(const float4*)&g_k[base + (size_t)(k0 + j) * 64 + ld];
            float4 vv = *(const float4*)&g_v[base + (size_t)(k0 + j) * 64 + ld];
            const int c = j ^ ld;
            KP[ld+0][c] = kv.x;  KP[ld+1][c] = kv.y;
            KP[ld+2][c] = kv.z;  KP[ld+3][c] = kv.w;
            *(float4*)&Vs[j][ld] = vv;
        }
        __syncthreads();

        float s[4][4] = {};
        #pragma unroll 16
        for (int d = 0; d < 64; ++d) {
            const int sz = d & 60;
            float4 qv = *(const float4*)&Qt[d][(ty << 2) ^ sz];
            float4 kv = *(const float4*)&KP[d][(tx << 2) ^ sz];
            float q_[4] = {qv.x, qv.y, qv.z, qv.w};
            float k_[4] = {kv.x, kv.y, kv.z, kv.w};
            #pragma unroll
            for (int i = 0; i < 4; ++i)
                #pragma unroll
                for (int j = 0; j < 4; ++j)
                    s[i][j] += q_[i] * k_[j];
        }

        float p[4][4];
        float al[4];
        #pragma unroll
        for (int i = 0; i < 4; ++i) {
            float4 mk = *(const float4*)&mask[(size_t)(q0 + (ty << 2) + i) * SS + k0 + (tx << 2)];
            float v0 = (s[i][0] + mk.x) * 0.125f;
            float v1 = (s[i][1] + mk.y) * 0.125f;
            float v2 = (s[i][2] + mk.z) * 0.125f;
            float v3 = (s[i][3] + mk.w) * 0.125f;
            float rmax = fmaxf(fmaxf(v0, v1), fmaxf(v2, v3));
            #pragma unroll
            for (int off = 8; off > 0; off >>= 1)
                rmax = fmaxf(rmax, __shfl_xor_sync(0xffffffffu, rmax, off, 16));
            const float mn = fmaxf(m_i[i], rmax);
            const float a  = __expf(m_i[i] - mn);
            m_i[i] = mn;
            float p0 = __expf(v0 - mn), p1 = __expf(v1 - mn);
            float p2 = __expf(v2 - mn), p3 = __expf(v3 - mn);
            float rs = p0 + p1 + p2 + p3;
            #pragma unroll
            for (int off = 8; off > 0; off >>= 1)
                rs += __shfl_xor_sync(0xffffffffu, rs, off, 16);
            l_i[i] = l_i[i] * a + rs;
            al[i] = a;
            p[i][0] = p0; p[i][1] = p1; p[i][2] = p2; p[i][3] = p3;
        }
        #pragma unroll
        for (int i = 0; i < 4; ++i)
            #pragma unroll
            for (int j = 0; j < 4; ++j)
                o[i][j] *= al[i];

        __syncthreads();
        #pragma unroll
        for (int jj = 0; jj < 4; ++jj) {
            const int j = (tx << 2) + jj;
            const int c = (ty << 2) ^ (tx << 2);
            float4 pv4 = make_float4(p[0][jj], p[1][jj], p[2][jj], p[3][jj]);
            *(float4*)&KP[j][c] = pv4;
        }
        __syncthreads();

        #pragma unroll 16
        for (int j = 0; j < 64; ++j) {
            const int sz = j & 60;
            float4 pv = *(const float4*)&KP[j][(ty << 2) ^ sz];
            float4 vv = *(const float4*)&Vs[j][tx << 2];
            float p_[4] = {pv.x, pv.y, pv.z, pv.w};
            float v_[4] = {vv.x, vv.y, vv.z, vv.w};
            #pragma unroll
            for (int i = 0; i < 4; ++i)
                #pragma unroll
                for (int cc = 0; cc < 4; ++cc)
                    o[i][cc] += p_[i] * v_[cc];
        }
    }

    // epilogue: normalize, bf16 hi/lo split to g_atth/g_attl [b][s][h*64+dh]
    const int b = bh / 12;
    const int h = bh % 12;
    #pragma unroll
    for (int i = 0; i < 4; ++i) {
        const float inv = 1.0f / l_i[i];
        const int srow = q0 + (ty << 2) + i;
        const size_t ob = ((size_t)(b * SS + srow)) * SD + h * 64 + (tx << 2);
        float x0 = o[i][0] * inv, x1 = o[i][1] * inv;
        float x2 = o[i][2] * inv, x3 = o[i][3] * inv;
        __nv_bfloat16 h0 = __float2bfloat16(x0);
        __nv_bfloat16 h1 = __float2bfloat16(x1);
        __nv_bfloat16 h2 = __float2bfloat16(x2);
        __nv_bfloat16 h3 = __float2bfloat16(x3);
        __nv_bfloat16 l0 = __float2bfloat16(x0 - __bfloat162float(h0));
        __nv_bfloat16 l1 = __float2bfloat16(x1 - __bfloat162float(h1));
        __nv_bfloat16 l2 = __float2bfloat16(x2 - __bfloat162float(h2));
        __nv_bfloat16 l3 = __float2bfloat16(x3 - __bfloat162float(h3));
        *(__nv_bfloat162*)(g_atth + ob)     = __nv_bfloat162(h0, h1);
        *(__nv_bfloat162*)(g_atth + ob + 2) = __nv_bfloat162(h2, h3);
        *(__nv_bfloat162*)(g_attl + ob)     = __nv_bfloat162(l0, l1);
        *(__nv_bfloat162*)(g_attl + ob + 2) = __nv_bfloat162(l2, l3);
    }
}

// ---------------------------------------------------------------------------
extern "C" void kernel_launch(void* const* d_in, const int* in_sizes, int n_in,
                              void* d_out, int out_size)
{
    const float* q    = (const float*)d_in[0];
    const float* k    = (const float*)d_in[1];
    const float* v    = (const float*)d_in[2];
    const float* mask = (const float*)d_in[3];
    const float* Wq   = (const float*)d_in[4];
    const float* bq   = (const float*)d_in[5];
    const float* Wk   = (const float*)d_in[6];
    const float* bk   = (const float*)d_in[7];
    const float* Wv   = (const float*)d_in[8];
    const float* bv   = (const float*)d_in[9];
    const float* Wo   = (const float*)d_in[10];
    const float* bo   = (const float*)d_in[11];
    float* out = (float*)d_out;

    (void)in_sizes; (void)n_in; (void)out_size;

    cudaFuncSetAttribute(gemm_tc<0>, cudaFuncAttributeMaxDynamicSharedMemorySize, SM_TOT);
    cudaFuncSetAttribute(gemm_tc<1>, cudaFuncAttributeMaxDynamicSharedMemorySize, SM_TOT);
    cudaFuncSetAttribute(gemm_tc<2>, cudaFuncAttributeMaxDynamicSharedMemorySize, SM_TOT);
    cudaFuncSetAttribute(gemm_tc<3>, cudaFuncAttributeMaxDynamicSharedMemorySize, SM_TOT);

    // fp32 -> bf16 hi/lo splits
    split_bf16<<<3072, 256>>>(q, 0, 0);
    split_bf16<<<3072, 256>>>(k, 0, 1);
    split_bf16<<<3072, 256>>>(v, 0, 2);
    split_bf16<<<576, 256>>>(Wq, 1, 0);
    split_bf16<<<576, 256>>>(Wk, 1, 1);
    split_bf16<<<576, 256>>>(Wv, 1, 2);
    split_bf16<<<576, 256>>>(Wo, 1, 3);

    dim3 gemm_grid(4096 / 128, 768 / 128);   // 32 x 6
    dim3 flash_grid(SS / 64, SB * SH);       // 32 x 24

    gemm_tc<1><<<gemm_grid, 512, SM_TOT>>>(bq, nullptr);
    gemm_tc<2><<<gemm_grid, 512, SM_TOT>>>(bk, nullptr);
    gemm_tc<3><<<gemm_grid, 512, SM_TOT>>>(bv, nullptr);
    flash_attn<<<flash_grid, 256>>>(mask);
    gemm_tc<0><<<gemm_grid, 512, SM_TOT>>>(bo, out);
}

// round 4
// speedup vs baseline: 2.6423x; 1.9915x over previous
#include <cuda_runtime.h>
#include <cuda_bf16.h>
#include <cstdint>

// B=2, S=2048, D=768, H=12, DH=64
#define SB 2
#define SS 2048
#define SD 768
#define SH 12
#define SDH 64

// ---------------------------------------------------------------------------
// Scratch (static device globals — no allocations allowed)
// ---------------------------------------------------------------------------
__device__ __nv_bfloat16 g_inh[3][4096*768];   // q,k,v inputs split hi
__device__ __nv_bfloat16 g_inl[3][4096*768];   // lo
__device__ __nv_bfloat16 g_wh[4][768*768];     // Wq,Wk,Wv,Wo hi
__device__ __nv_bfloat16 g_wl[4][768*768];     // lo

__device__ __nv_bfloat16 g_qh[SB*SH*SS*SDH];   // projected q/k/v, [bh][s][dh], hi/lo
__device__ __nv_bfloat16 g_ql[SB*SH*SS*SDH];
__device__ __nv_bfloat16 g_kh[SB*SH*SS*SDH];
__device__ __nv_bfloat16 g_kl[SB*SH*SS*SDH];
__device__ __nv_bfloat16 g_vh[SB*SH*SS*SDH];
__device__ __nv_bfloat16 g_vl[SB*SH*SS*SDH];

__device__ __nv_bfloat16 g_atth[4096*768];     // attention output split hi
__device__ __nv_bfloat16 g_attl[4096*768];     // lo

// ---------------------------------------------------------------------------
__device__ __forceinline__ uint32_t smem_u32(const void* p) {
    uint32_t a;
    asm("{ .reg .u64 t; cvta.to.shared.u64 t, %1; cvt.u32.u64 %0, t; }"
        : "=r"(a) : "l"(p));
    return a;
}

#define LDSM_X4(r0, r1, r2, r3, addr) \
    asm volatile("ldmatrix.sync.aligned.m8n8.x4.shared.b16 {%0,%1,%2,%3}, [%4];" \
        : "=r"(r0), "=r"(r1), "=r"(r2), "=r"(r3) : "r"(addr))

#define LDSM_X4_T(r0, r1, r2, r3, addr) \
    asm volatile("ldmatrix.sync.aligned.m8n8.x4.trans.shared.b16 {%0,%1,%2,%3}, [%4];" \
        : "=r"(r0), "=r"(r1), "=r"(r2), "=r"(r3) : "r"(addr))

#define MMA_BF16(d, a, b) \
    asm volatile("mma.sync.aligned.m16n8k16.row.col.f32.bf16.bf16.f32 " \
        "{%0,%1,%2,%3}, {%4,%5,%6,%7}, {%8,%9}, {%0,%1,%2,%3};" \
        : "+f"((d)[0]), "+f"((d)[1]), "+f"((d)[2]), "+f"((d)[3]) \
        : "r"((a)[0]), "r"((a)[1]), "r"((a)[2]), "r"((a)[3]), \
          "r"((b)[0]), "r"((b)[1]))

#define CP_ASYNC16(s, g) \
    asm volatile("cp.async.cg.shared.global [%0], [%1], 16;" :: "r"(s), "l"(g))
#define CP_COMMIT() asm volatile("cp.async.commit_group;" ::: "memory")
#define CP_WAIT0()  asm volatile("cp.async.wait_group 0;" ::: "memory")

__device__ __forceinline__ uint32_t bpack(__nv_bfloat16 a, __nv_bfloat16 b) {
    __nv_bfloat162 t(a, b);
    return *reinterpret_cast<uint32_t*>(&t);
}

// ---------------------------------------------------------------------------
// fp32 -> bf16 (hi, lo) split.  kind 0: inputs; kind 1: weights.
// ---------------------------------------------------------------------------
__global__ __launch_bounds__(256) void split_bf16(const float* __restrict__ x,
                                                  int kind, int idx) {
    const int i = (blockIdx.x * 256 + threadIdx.x) * 4;
    __nv_bfloat16* hi;
    __nv_bfloat16* lo;
    if (kind == 0) { hi = g_inh[idx]; lo = g_inl[idx]; }
    else           { hi = g_wh[idx];  lo = g_wl[idx];  }
    float4 v = *(const float4*)(x + i);
    __nv_bfloat16 h0 = __float2bfloat16(v.x);
    __nv_bfloat16 h1 = __float2bfloat16(v.y);
    __nv_bfloat16 h2 = __float2bfloat16(v.z);
    __nv_bfloat16 h3 = __float2bfloat16(v.w);
    __nv_bfloat16 l0 = __float2bfloat16(v.x - __bfloat162float(h0));
    __nv_bfloat16 l1 = __float2bfloat16(v.y - __bfloat162float(h1));
    __nv_bfloat16 l2 = __float2bfloat16(v.z - __bfloat162float(h2));
    __nv_bfloat16 l3 = __float2bfloat16(v.w - __bfloat162float(h3));
    *(__nv_bfloat162*)(hi + i)     = __nv_bfloat162(h0, h1);
    *(__nv_bfloat162*)(hi + i + 2) = __nv_bfloat162(h2, h3);
    *(__nv_bfloat162*)(lo + i)     = __nv_bfloat162(l0, l1);
    *(__nv_bfloat162*)(lo + i + 2) = __nv_bfloat162(l2, l3);
}

// ---------------------------------------------------------------------------
// HMMA GEMM: C[m,n] = sum_k A[m,k] * W[n,k] + bias[n]
// 2-term bf16 split: C = Ah*Bh + Ah*Bl + Al*Bh  (fp32 accum in registers)
// MODE 1/2/3: scatter bf16 hi/lo to g_{q,k,v}{h,l} [bh][s][dh].
// MODE 0:     A = g_atth/l, W = Wo, fp32 store to `out`.
// ---------------------------------------------------------------------------
#define SM_BIAS 0
#define SM_AH   1024
#define SM_AL   (1024 + 16384)
#define SM_BH   (1024 + 32768)
#define SM_BL   (1024 + 49152)
#define SM_TOT  (1024 + 65536)

template<int MODE>
__global__ __launch_bounds__(512, 1) void gemm_tc(const float* __restrict__ bias,
                                                  float* __restrict__ out) {
    extern __shared__ __align__(1024) char smem[];
    const int tid = threadIdx.x;
    const int wid = tid >> 5;
    const int lid = tid & 31;
    const int m0 = blockIdx.x << 7;
    const int n0 = blockIdx.y << 7;
    const uint32_t sb = smem_u32(smem);

    const int widx = (MODE == 0) ? 3 : (MODE - 1);
    const __nv_bfloat16* Ah = (MODE == 0) ? g_atth : g_inh[widx];
    const __nv_bfloat16* Al = (MODE == 0) ? g_attl : g_inl[widx];
    const __nv_bfloat16* Bh = g_wh[widx];
    const __nv_bfloat16* Bl = g_wl[widx];

    if (tid < 32)
        ((float4*)(smem + SM_BIAS))[tid] = ((const float4*)(bias + n0))[tid];

    const int i0 = tid, i1 = tid + 512;
    const int r0_ = i0 >> 3, u0 = i0 & 7;
    const int r1_ = i1 >> 3, u1 = i1 & 7;
    const uint32_t so0 = (uint32_t)(r0_ * 128 + ((u0 * 16) ^ ((r0_ & 7) << 4)));
    const uint32_t so1 = (uint32_t)(r1_ * 128 + ((u1 * 16) ^ ((r1_ & 7) << 4)));

    float acc[2][4][4];
    #pragma unroll
    for (int mt = 0; mt < 2; ++mt)
        #pragma unroll
        for (int nt = 0; nt < 4; ++nt)
            #pragma unroll
            for (int e = 0; e < 4; ++e) acc[mt][nt][e] = 0.f;

    const int wm = (wid >> 2) << 5;
    const int wn = (wid & 3) << 5;
    const int lq = lid >> 3;
    const int lr = lid & 7;

    uint4 pa0, pa1, pl0, pl1, pb0, pb1, pq0, pq1;
    {
        const int ka = 0;
        pa0 = *(const uint4*)(Ah + (size_t)(m0 + r0_) * 768 + ka + u0 * 8);
        pa1 = *(const uint4*)(Ah + (size_t)(m0 + r1_) * 768 + ka + u1 * 8);
        pl0 = *(const uint4*)(Al + (size_t)(m0 + r0_) * 768 + ka + u0 * 8);
        pl1 = *(const uint4*)(Al + (size_t)(m0 + r1_) * 768 + ka + u1 * 8);
        pb0 = *(const uint4*)(Bh + (size_t)(n0 + r0_) * 768 + ka + u0 * 8);
        pb1 = *(const uint4*)(Bh + (size_t)(n0 + r1_) * 768 + ka + u1 * 8);
        pq0 = *(const uint4*)(Bl + (size_t)(n0 + r0_) * 768 + ka + u0 * 8);
        pq1 = *(const uint4*)(Bl + (size_t)(n0 + r1_) * 768 + ka + u1 * 8);
    }

    for (int c = 0; c < 12; ++c) {
        *(uint4*)(smem + SM_AH + so0) = pa0;  *(uint4*)(smem + SM_AH + so1) = pa1;
        *(uint4*)(smem + SM_AL + so0) = pl0;  *(uint4*)(smem + SM_AL + so1) = pl1;
        *(uint4*)(smem + SM_BH + so0) = pb0;  *(uint4*)(smem + SM_BH + so1) = pb1;
        *(uint4*)(smem + SM_BL + so0) = pq0;  *(uint4*)(smem + SM_BL + so1) = pq1;
        __syncthreads();

        if (c < 11) {
            const int ka = (c + 1) << 6;
            pa0 = *(const uint4*)(Ah + (size_t)(m0 + r0_) * 768 + ka + u0 * 8);
            pa1 = *(const uint4*)(Ah + (size_t)(m0 + r1_) * 768 + ka + u1 * 8);
            pl0 = *(const uint4*)(Al + (size_t)(m0 + r0_) * 768 + ka + u0 * 8);
            pl1 = *(const uint4*)(Al + (size_t)(m0 + r1_) * 768 + ka + u1 * 8);
            pb0 = *(const uint4*)(Bh + (size_t)(n0 + r0_) * 768 + ka + u0 * 8);
            pb1 = *(const uint4*)(Bh + (size_t)(n0 + r1_) * 768 + ka + u1 * 8);
            pq0 = *(const uint4*)(Bl + (size_t)(n0 + r0_) * 768 + ka + u0 * 8);
            pq1 = *(const uint4*)(Bl + (size_t)(n0 + r1_) * 768 + ka + u1 * 8);
        }

        #pragma unroll
        for (int ks = 0; ks < 4; ++ks) {
            uint32_t ah[2][4], alr[2][4];
            #pragma unroll
            for (int mt = 0; mt < 2; ++mt) {
                const int row = wm + mt * 16 + ((lq & 1) << 3) + lr;
                const int kc  = (ks << 4) + ((lq >> 1) << 3);
                const uint32_t off = (uint32_t)(row * 128 + ((kc * 2) ^ ((row & 7) << 4)));
                LDSM_X4(ah[mt][0], ah[mt][1], ah[mt][2], ah[mt][3], sb + SM_AH + off);
                LDSM_X4(alr[mt][0], alr[mt][1], alr[mt][2], alr[mt][3], sb + SM_AL + off);
            }
            uint32_t bh[4][2], bl[4][2];
            #pragma unroll
            for (int half = 0; half < 2; ++half) {
                const int nrow = wn + half * 16 + ((lq >> 1) << 3) + lr;
                const int kc   = (ks << 4) + ((lq & 1) << 3);
                const uint32_t off = (uint32_t)(nrow * 128 + ((kc * 2) ^ ((nrow & 7) << 4)));
                uint32_t t0, t1, t2, t3;
                LDSM_X4(t0, t1, t2, t3, sb + SM_BH + off);
                bh[half * 2][0] = t0;     bh[half * 2][1] = t1;
                bh[half * 2 + 1][0] = t2; bh[half * 2 + 1][1] = t3;
                LDSM_X4(t0, t1, t2, t3, sb + SM_BL + off);
                bl[half * 2][0] = t0;     bl[half * 2][1] = t1;
                bl[half * 2 + 1][0] = t2; bl[half * 2 + 1][1] = t3;
            }
            #pragma unroll
            for (int mt = 0; mt < 2; ++mt)
                #pragma unroll
                for (int nt = 0; nt < 4; ++nt) {
                    MMA_BF16(acc[mt][nt], ah[mt], bh[nt]);
                    MMA_BF16(acc[mt][nt], ah[mt], bl[nt]);
                    MMA_BF16(acc[mt][nt], alr[mt], bh[nt]);
                }
        }
        __syncthreads();
    }

    // epilogue
    const int gID = lid >> 2;
    const int tc  = (lid & 3) << 1;
    const float* bs = (const float*)(smem + SM_BIAS);
    #pragma unroll
    for (int mt = 0; mt < 2; ++mt)
        #pragma unroll
        for (int nt = 0; nt < 4; ++nt) {
            const int colr = wn + nt * 8 + tc;
            const float b0 = bs[colr], b1 = bs[colr + 1];
            #pragma unroll
            for (int rh = 0; rh < 2; ++rh) {
                const int m = m0 + wm + mt * 16 + gID + rh * 8;
                float rx = acc[mt][nt][rh * 2 + 0] + b0;
                float ry = acc[mt][nt][rh * 2 + 1] + b1;
                if (MODE != 0) {
                    __nv_bfloat16* dh_ = (MODE == 1) ? g_qh : (MODE == 2) ? g_kh : g_vh;
                    __nv_bfloat16* dl_ = (MODE == 1) ? g_ql : (MODE == 2) ? g_kl : g_vl;
                    const int b = m >> 11;
                    const int s = m & 2047;
                    const int head = (n0 + colr) >> 6;
                    const int dh   = (n0 + colr) & 63;
                    const size_t o = ((size_t)((b * 12 + head) << 11) + s) * 64 + dh;
                    __nv_bfloat16 hx = __float2bfloat16(rx);
                    __nv_bfloat16 hy = __float2bfloat16(ry);
                    __nv_bfloat16 lx = __float2bfloat16(rx - __bfloat162float(hx));
                    __nv_bfloat16 ly = __float2bfloat16(ry - __bfloat162float(hy));
                    *(__nv_bfloat162*)(dh_ + o) = __nv_bfloat162(hx, hy);
                    *(__nv_bfloat162*)(dl_ + o) = __nv_bfloat162(lx, ly);
                } else {
                    float2 r = make_float2(rx, ry);
                    *(float2*)&out[(size_t)m * 768 + n0 + colr] = r;
                }
            }
        }
}

// ---------------------------------------------------------------------------
// Flash attention on HMMA (bf16 hi/lo split, fp32 accum).
// CTA: 128 q-rows of one (b,h); 8 warps x 16 rows. Key tiles of 128,
// double-buffered K/V in smem via cp.async. Q fragments in registers.
// S = (Q Kt + mask)/8; online softmax; O += P V (V via ldmatrix.trans).
// ---------------------------------------------------------------------------
#define FS_QH  0
#define FS_QL  16384
#define FS_KV  32768                 // + buf*65536 : KH, KL, VH, VL (16K each)
#define FS_TOT (32768 + 2 * 65536)   // 163840

__device__ __forceinline__ void fa_load_tile(uint32_t sb, int tid, size_t base,
                                             int t, int buf) {
    const uint32_t kb = FS_KV + (uint32_t)buf * 65536u;
    const int s0 = t << 7;
    #pragma unroll
    for (int r4 = 0; r4 < 4; ++r4) {
        const int u = r4 * 256 + tid;
        const int row = u >> 3, c16 = u & 7;
        const uint32_t so = (uint32_t)(row * 128 + ((c16 * 16) ^ ((row & 7) << 4)));
        const size_t g = base + (size_t)(s0 + row) * 64 + c16 * 8;
        CP_ASYNC16(sb + kb + so,         (const char*)(g_kh + g));
        CP_ASYNC16(sb + kb + 16384 + so, (const char*)(g_kl + g));
        CP_ASYNC16(sb + kb + 32768 + so, (const char*)(g_vh + g));
        CP_ASYNC16(sb + kb + 49152 + so, (const char*)(g_vl + g));
    }
}

__global__ __launch_bounds__(256, 1) void flash_mma(const float* __restrict__ mask)
{
    extern __shared__ __align__(1024) char smem[];
    const uint32_t sb = smem_u32(smem);
    const int tid = threadIdx.x;
    const int wid = tid >> 5;
    const int lid = tid & 31;
    const int lq  = lid >> 3;
    const int lr  = lid & 7;
    const int q0  = blockIdx.x << 7;
    const int bh  = blockIdx.y;
    const size_t base = (size_t)bh * SS * SDH;

    // prologue: Q tile + KV tile 0 in one cp.async group
    #pragma unroll
    for (int r4 = 0; r4 < 4; ++r4) {
        const int u = r4 * 256 + tid;
        const int row = u >> 3, c16 = u & 7;
        const uint32_t so = (uint32_t)(row * 128 + ((c16 * 16) ^ ((row & 7) << 4)));
        const size_t g = base + (size_t)(q0 + row) * 64 + c16 * 8;
        CP_ASYNC16(sb + FS_QH + so, (const char*)(g_qh + g));
        CP_ASYNC16(sb + FS_QL + so, (const char*)(g_ql + g));
    }
    fa_load_tile(sb, tid, base, 0, 0);
    CP_COMMIT();

    uint32_t qh[4][4], ql[4][4];
    float m_[2] = {-1e30f, -1e30f};
    float l_[2] = {0.f, 0.f};
    float o[8][4];
    #pragma unroll
    for (int d = 0; d < 8; ++d)
        #pragma unroll
        for (int e = 0; e < 4; ++e) o[d][e] = 0.f;

    for (int t = 0; t < 16; ++t) {
        CP_WAIT0();
        __syncthreads();

        if (t == 0) {
            #pragma unroll
            for (int ks = 0; ks < 4; ++ks) {
                const int row = (wid << 4) + ((lq & 1) << 3) + lr;
                const int kc  = (ks << 4) + ((lq >> 1) << 3);
                const uint32_t off = (uint32_t)(row * 128 + ((kc * 2) ^ ((row & 7) << 4)));
                LDSM_X4(qh[ks][0], qh[ks][1], qh[ks][2], qh[ks][3], sb + FS_QH + off);
                LDSM_X4(ql[ks][0], ql[ks][1], ql[ks][2], ql[ks][3], sb + FS_QL + off);
            }
        }
        if (t < 15) {
            fa_load_tile(sb, tid, base, t + 1, (t + 1) & 1);
            CP_COMMIT();
        }

        const uint32_t kb = FS_KV + (uint32_t)(t & 1) * 65536u;

        // ---- S = Q K^T (hi/lo split) ----
        float s_[16][4];
        #pragma unroll
        for (int nt = 0; nt < 16; ++nt)
            #pragma unroll
            for (int e = 0; e < 4; ++e) s_[nt][e] = 0.f;

        #pragma unroll
        for (int ks = 0; ks < 4; ++ks) {
            #pragma unroll
            for (int hf = 0; hf < 8; ++hf) {
                const int nrow = (hf << 4) + ((lq >> 1) << 3) + lr;
                const int kc   = (ks << 4) + ((lq & 1) << 3);
                const uint32_t off = (uint32_t)(nrow * 128 + ((kc * 2) ^ ((nrow & 7) << 4)));
                uint32_t a0, a1, a2, a3, b0, b1, b2, b3;
                LDSM_X4(a0, a1, a2, a3, sb + kb + off);            // K hi
                LDSM_X4(b0, b1, b2, b3, sb + kb + 16384 + off);    // K lo
                uint32_t kh0[2] = {a0, a1}, kh1[2] = {a2, a3};
                uint32_t kl0[2] = {b0, b1}, kl1[2] = {b2, b3};
                MMA_BF16(s_[hf * 2],     qh[ks], kh0);
                MMA_BF16(s_[hf * 2],     qh[ks], kl0);
                MMA_BF16(s_[hf * 2],     ql[ks], kh0);
                MMA_BF16(s_[hf * 2 + 1], qh[ks], kh1);
                MMA_BF16(s_[hf * 2 + 1], qh[ks], kl1);
                MMA_BF16(s_[hf * 2 + 1], ql[ks], kh1);
            }
        }

        // ---- mask + scale + online softmax ----
        const int rowA = q0 + (wid << 4) + (lid >> 2);
        const float* mrowA = mask + (size_t)rowA * SS + (t << 7) + ((lid & 3) << 1);
        const float* mrowB = mrowA + 8 * SS;
        float rmA = -1e30f, rmB = -1e30f;
        #pragma unroll
        for (int nt = 0; nt < 16; ++nt) {
            float2 ma = *(const float2*)(mrowA + nt * 8);
            float2 mb = *(const float2*)(mrowB + nt * 8);
            s_[nt][0] = (s_[nt][0] + ma.x) * 0.125f;
            s_[nt][1] = (s_[nt][1] + ma.y) * 0.125f;
            s_[nt][2] = (s_[nt][2] + mb.x) * 0.125f;
            s_[nt][3] = (s_[nt][3] + mb.y) * 0.125f;
            rmA = fmaxf(rmA, fmaxf(s_[nt][0], s_[nt][1]));
            rmB = fmaxf(rmB, fmaxf(s_[nt][2], s_[nt][3]));
        }
        rmA = fmaxf(rmA, __shfl_xor_sync(0xffffffffu, rmA, 1));
        rmA = fmaxf(rmA, __shfl_xor_sync(0xffffffffu, rmA, 2));
        rmB = fmaxf(rmB, __shfl_xor_sync(0xffffffffu, rmB, 1));
        rmB = fmaxf(rmB, __shfl_xor_sync(0xffffffffu, rmB, 2));
        const float mA = fmaxf(m_[0], rmA), mB = fmaxf(m_[1], rmB);
        const float aA = __expf(m_[0] - mA), aB = __expf(m_[1] - mB);
        m_[0] = mA; m_[1] = mB;

        float sA = 0.f, sB = 0.f;
        #pragma unroll
        for (int nt = 0; nt < 16; ++nt) {
            s_[nt][0] = __expf(s_[nt][0] - mA);
            s_[nt][1] = __expf(s_[nt][1] - mA);
            s_[nt][2] = __expf(s_[nt][2] - mB);
            s_[nt][3] = __expf(s_[nt][3] - mB);
            sA += s_[nt][0] + s_[nt][1];
            sB += s_[nt][2] + s_[nt][3];
        }
        sA += __shfl_xor_sync(0xffffffffu, sA, 1);
        sA += __shfl_xor_sync(0xffffffffu, sA, 2);
        sB += __shfl_xor_sync(0xffffffffu, sB, 1);
        sB += __shfl_xor_sync(0xffffffffu, sB, 2);
        l_[0] = l_[0] * aA + sA;
        l_[1] = l_[1] * aB + sB;

        #pragma unroll
        for (int d = 0; d < 8; ++d) {
            o[d][0] *= aA; o[d][1] *= aA;
            o[d][2] *= aB; o[d][3] *= aB;
        }

        // ---- O += P V (hi/lo split, V via ldmatrix.trans) ----
        #pragma unroll
        for (int ks = 0; ks < 8; ++ks) {
            const float x0 = s_[2 * ks][0], x1 = s_[2 * ks][1];
            const float x2 = s_[2 * ks][2], x3 = s_[2 * ks][3];
            const float y0 = s_[2 * ks + 1][0], y1 = s_[2 * ks + 1][1];
            const float y2 = s_[2 * ks + 1][2], y3 = s_[2 * ks + 1][3];
            __nv_bfloat16 hx0 = __float2bfloat16(x0), hx1 = __float2bfloat16(x1);
            __nv_bfloat16 hx2 = __float2bfloat16(x2), hx3 = __float2bfloat16(x3);
            __nv_bfloat16 hy0 = __float2bfloat16(y0), hy1 = __float2bfloat16(y1);
            __nv_bfloat16 hy2 = __float2bfloat16(y2), hy3 = __float2bfloat16(y3);
            uint32_t ph[4], pl[4];
            ph[0] = bpack(hx0, hx1);  ph[1] = bpack(hx2, hx3);
            ph[2] = bpack(hy0, hy1);  ph[3] = bpack(hy2, hy3);
            pl[0] = bpack(__float2bfloat16(x0 - __bfloat162float(hx0)),
                          __float2bfloat16(x1 - __bfloat162float(hx1)));
            pl[1] = bpack(__float2bfloat16(x2 - __bfloat162float(hx2)),
                          __float2bfloat16(x3 - __bfloat162float(hx3)));
            pl[2] = bpack(__float2bfloat16(y0 - __bfloat162float(hy0)),
                          __float2bfloat16(y1 - __bfloat162float(hy1)));
            pl[3] = bpack(__float2bfloat16(y2 - __bfloat162float(hy2)),
                          __float2bfloat16(y3 - __bfloat162float(hy3)));

            #pragma unroll
            for (int dp = 0; dp < 4; ++dp) {
                const int j = (ks << 4) + ((lq & 1) << 3) + lr;
                const int d = (dp << 4) + ((lq >> 1) << 3);
                const uint32_t off = (uint32_t)(j * 128 + ((d * 2) ^ ((j & 7) << 4)));
                uint32_t v0, v1, v2, v3, w0, w1, w2, w3;
                LDSM_X4_T(v0, v1, v2, v3, sb + kb + 32768 + off);   // V hi
                LDSM_X4_T(w0, w1, w2, w3, sb + kb + 49152 + off);   // V lo
                uint32_t vh0[2] = {v0, v1}, vh1[2] = {v2, v3};
                uint32_t vl0[2] = {w0, w1}, vl1[2] = {w2, w3};
                MMA_BF16(o[dp * 2],     ph, vh0);
                MMA_BF16(o[dp * 2],     ph, vl0);
                MMA_BF16(o[dp * 2],     pl, vh0);
                MMA_BF16(o[dp * 2 + 1], ph, vh1);
                MMA_BF16(o[dp * 2 + 1], ph, vl1);
                MMA_BF16(o[dp * 2 + 1], pl, vh1);
            }
        }
    }

    // ---- epilogue: normalize, bf16 hi/lo split to g_atth/g_attl ----
    const int b = bh / 12;
    const int h = bh % 12;
    const float invA = 1.f / l_[0];
    const float invB = 1.f / l_[1];
    const int sA_ = q0 + (wid << 4) + (lid >> 2);
    const int sB_ = sA_ + 8;
    #pragma unroll
    for (int dp = 0; dp < 8; ++dp) {
        const int d = dp * 8 + ((lid & 3) << 1);
        const size_t oa = ((size_t)(b * SS + sA_)) * SD + h * 64 + d;
        const size_t ob = ((size_t)(b * SS + sB_)) * SD + h * 64 + d;
        const float xa0 = o[dp][0] * invA, xa1 = o[dp][1] * invA;
        const float xb0 = o[dp][2] * invB, xb1 = o[dp][3] * invB;
        __nv_bfloat16 ha0 = __float2bfloat16(xa0), ha1 = __float2bfloat16(xa1);
        __nv_bfloat16 hb0 = __float2bfloat16(xb0), hb1 = __float2bfloat16(xb1);
        *(__nv_bfloat162*)(g_atth + oa) = __nv_bfloat162(ha0, ha1);
        *(__nv_bfloat162*)(g_atth + ob) = __nv_bfloat162(hb0, hb1);
        *(__nv_bfloat162*)(g_attl + oa) =
            __nv_bfloat162(__float2bfloat16(xa0 - __bfloat162float(ha0)),
                           __float2bfloat16(xa1 - __bfloat162float(ha1)));
        *(__nv_bfloat162*)(g_attl + ob) =
            __nv_bfloat162(__float2bfloat16(xb0 - __bfloat162float(hb0)),
                           __float2bfloat16(xb1 - __bfloat162float(hb1)));
    }
}

// ---------------------------------------------------------------------------
extern "C" void kernel_launch(void* const* d_in, const int* in_sizes, int n_in,
                              void* d_out, int out_size)
{
    const float* q    = (const float*)d_in[0];
    const float* k    = (const float*)d_in[1];
    const float* v    = (const float*)d_in[2];
    const float* mask = (const float*)d_in[3];
    const float* Wq   = (const float*)d_in[4];
    const float* bq   = (const float*)d_in[5];
    const float* Wk   = (const float*)d_in[6];
    const float* bk   = (const float*)d_in[7];
    const float* Wv   = (const float*)d_in[8];
    const float* bv   = (const float*)d_in[9];
    const float* Wo   = (const float*)d_in[10];
    const float* bo   = (const float*)d_in[11];
    float* out = (float*)d_out;

    (void)in_sizes; (void)n_in; (void)out_size;

    cudaFuncSetAttribute(gemm_tc<0>, cudaFuncAttributeMaxDynamicSharedMemorySize, SM_TOT);
    cudaFuncSetAttribute(gemm_tc<1>, cudaFuncAttributeMaxDynamicSharedMemorySize, SM_TOT);
    cudaFuncSetAttribute(gemm_tc<2>, cudaFuncAttributeMaxDynamicSharedMemorySize, SM_TOT);
    cudaFuncSetAttribute(gemm_tc<3>, cudaFuncAttributeMaxDynamicSharedMemorySize, SM_TOT);
    cudaFuncSetAttribute(flash_mma,  cudaFuncAttributeMaxDynamicSharedMemorySize, FS_TOT);

    // fp32 -> bf16 hi/lo splits
    split_bf16<<<3072, 256>>>(q, 0, 0);
    split_bf16<<<3072, 256>>>(k, 0, 1);
    split_bf16<<<3072, 256>>>(v, 0, 2);
    split_bf16<<<576, 256>>>(Wq, 1, 0);
    split_bf16<<<576, 256>>>(Wk, 1, 1);
    split_bf16<<<576, 256>>>(Wv, 1, 2);
    split_bf16<<<576, 256>>>(Wo, 1, 3);

    dim3 gemm_grid(4096 / 128, 768 / 128);   // 32 x 6
    dim3 flash_grid(SS / 128, SB * SH);      // 16 x 24

    gemm_tc<1><<<gemm_grid, 512, SM_TOT>>>(bq, nullptr);
    gemm_tc<2><<<gemm_grid, 512, SM_TOT>>>(bk, nullptr);
    gemm_tc<3><<<gemm_grid, 512, SM_TOT>>>(bv, nullptr);
    flash_mma<<<flash_grid, 256, FS_TOT>>>(mask);
    gemm_tc<0><<<gemm_grid, 512, SM_TOT>>>(bo, out);
}

// round 5
// speedup vs baseline: 3.0175x; 1.1420x over previous
#include <cuda_runtime.h>
#include <cuda_bf16.h>
#include <cstdint>

// B=2, S=2048, D=768, H=12, DH=64
#define SB 2
#define SS 2048
#define SD 768
#define SH 12
#define SDH 64

// ---------------------------------------------------------------------------
// Scratch (static device globals — no allocations allowed)
// ---------------------------------------------------------------------------
__device__ __nv_bfloat16 g_inh[3][4096*768];   // q,k,v inputs split hi
__device__ __nv_bfloat16 g_inl[3][4096*768];   // lo
__device__ __nv_bfloat16 g_wh[4][768*768];     // Wq,Wk,Wv,Wo hi
__device__ __nv_bfloat16 g_wl[4][768*768];     // lo

__device__ __nv_bfloat16 g_qh[SB*SH*SS*SDH];   // projected q/k/v, [bh][s][dh], hi/lo
__device__ __nv_bfloat16 g_ql[SB*SH*SS*SDH];
__device__ __nv_bfloat16 g_kh[SB*SH*SS*SDH];
__device__ __nv_bfloat16 g_kl[SB*SH*SS*SDH];
__device__ __nv_bfloat16 g_vh[SB*SH*SS*SDH];
__device__ __nv_bfloat16 g_vl[SB*SH*SS*SDH];

__device__ __nv_bfloat16 g_atth[4096*768];     // attention output split hi
__device__ __nv_bfloat16 g_attl[4096*768];     // lo

// ---------------------------------------------------------------------------
__device__ __forceinline__ uint32_t smem_u32(const void* p) {
    uint32_t a;
    asm("{ .reg .u64 t; cvta.to.shared.u64 t, %1; cvt.u32.u64 %0, t; }"
        : "=r"(a) : "l"(p));
    return a;
}

#define LDSM_X4(r0, r1, r2, r3, addr) \
    asm volatile("ldmatrix.sync.aligned.m8n8.x4.shared.b16 {%0,%1,%2,%3}, [%4];" \
        : "=r"(r0), "=r"(r1), "=r"(r2), "=r"(r3) : "r"(addr))

#define LDSM_X4_T(r0, r1, r2, r3, addr) \
    asm volatile("ldmatrix.sync.aligned.m8n8.x4.trans.shared.b16 {%0,%1,%2,%3}, [%4];" \
        : "=r"(r0), "=r"(r1), "=r"(r2), "=r"(r3) : "r"(addr))

#define MMA_BF16(d, a, b) \
    asm volatile("mma.sync.aligned.m16n8k16.row.col.f32.bf16.bf16.f32 " \
        "{%0,%1,%2,%3}, {%4,%5,%6,%7}, {%8,%9}, {%0,%1,%2,%3};" \
        : "+f"((d)[0]), "+f"((d)[1]), "+f"((d)[2]), "+f"((d)[3]) \
        : "r"((a)[0]), "r"((a)[1]), "r"((a)[2]), "r"((a)[3]), \
          "r"((b)[0]), "r"((b)[1]))

#define CP_ASYNC16(s, g) \
    asm volatile("cp.async.cg.shared.global [%0], [%1], 16;" :: "r"(s), "l"(g))
#define CP_COMMIT() asm volatile("cp.async.commit_group;" ::: "memory")
#define CP_WAIT0()  asm volatile("cp.async.wait_group 0;" ::: "memory")

__device__ __forceinline__ uint32_t bpack(__nv_bfloat16 a, __nv_bfloat16 b) {
    __nv_bfloat162 t(a, b);
    return *reinterpret_cast<uint32_t*>(&t);
}

// ---------------------------------------------------------------------------
// fp32 -> bf16 (hi, lo) split.
// split_in: one input (q/k/v) per launch (kept separate for profiler indexing).
// split_w:  all 4 weight matrices in one launch (blockIdx.y = idx).
// ---------------------------------------------------------------------------
__device__ __forceinline__ void split4(const float* __restrict__ x,
                                       __nv_bfloat16* __restrict__ hi,
                                       __nv_bfloat16* __restrict__ lo, int i) {
    float4 v = *(const float4*)(x + i);
    __nv_bfloat16 h0 = __float2bfloat16(v.x);
    __nv_bfloat16 h1 = __float2bfloat16(v.y);
    __nv_bfloat16 h2 = __float2bfloat16(v.z);
    __nv_bfloat16 h3 = __float2bfloat16(v.w);
    __nv_bfloat16 l0 = __float2bfloat16(v.x - __bfloat162float(h0));
    __nv_bfloat16 l1 = __float2bfloat16(v.y - __bfloat162float(h1));
    __nv_bfloat16 l2 = __float2bfloat16(v.z - __bfloat162float(h2));
    __nv_bfloat16 l3 = __float2bfloat16(v.w - __bfloat162float(h3));
    *(__nv_bfloat162*)(hi + i)     = __nv_bfloat162(h0, h1);
    *(__nv_bfloat162*)(hi + i + 2) = __nv_bfloat162(h2, h3);
    *(__nv_bfloat162*)(lo + i)     = __nv_bfloat162(l0, l1);
    *(__nv_bfloat162*)(lo + i + 2) = __nv_bfloat162(l2, l3);
}

__global__ __launch_bounds__(256) void split_in(const float* __restrict__ x, int idx) {
    const int i = (blockIdx.x * 256 + threadIdx.x) * 4;
    split4(x, g_inh[idx], g_inl[idx], i);
}

__global__ __launch_bounds__(256) void split_w(const float* __restrict__ w0,
                                               const float* __restrict__ w1,
                                               const float* __restrict__ w2,
                                               const float* __restrict__ w3) {
    const int idx = blockIdx.y;
    const float* x = (idx == 0) ? w0 : (idx == 1) ? w1 : (idx == 2) ? w2 : w3;
    const int i = (blockIdx.x * 256 + threadIdx.x) * 4;
    split4(x, g_wh[idx], g_wl[idx], i);
}

// ---------------------------------------------------------------------------
// HMMA GEMM core. C[m,n] = sum_k A[m,k]*W[n,k] + bias[n]
// 2-term bf16 split: C = Ah*Bh + Ah*Bl + Al*Bh (fp32 accum).
// CTA 128x128, 512 threads, K chunks of 64, reg-prefetch double buffer.
// ---------------------------------------------------------------------------
#define SM_BIAS 0
#define SM_AH   1024
#define SM_AL   (1024 + 16384)
#define SM_BH   (1024 + 32768)
#define SM_BL   (1024 + 49152)
#define SM_TOT  (1024 + 65536)

// SCATTER=true: write bf16 hi/lo to dh_/dl_ [bh][s][dh]; else fp32 rows to out.
template<bool SCATTER>
__device__ __forceinline__ void gemm_body(
    const __nv_bfloat16* __restrict__ Ah, const __nv_bfloat16* __restrict__ Al,
    const __nv_bfloat16* __restrict__ Bh, const __nv_bfloat16* __restrict__ Bl,
    const float* __restrict__ bias,
    __nv_bfloat16* __restrict__ dh_, __nv_bfloat16* __restrict__ dl_,
    float* __restrict__ out, int m0, int n0, char* smem)
{
    const int tid = threadIdx.x;
    const int wid = tid >> 5;
    const int lid = tid & 31;
    const uint32_t sb = smem_u32(smem);

    if (tid < 32)
        ((float4*)(smem + SM_BIAS))[tid] = ((const float4*)(bias + n0))[tid];

    const int i0 = tid, i1 = tid + 512;
    const int r0_ = i0 >> 3, u0 = i0 & 7;
    const int r1_ = i1 >> 3, u1 = i1 & 7;
    const uint32_t so0 = (uint32_t)(r0_ * 128 + ((u0 * 16) ^ ((r0_ & 7) << 4)));
    const uint32_t so1 = (uint32_t)(r1_ * 128 + ((u1 * 16) ^ ((r1_ & 7) << 4)));

    float acc[2][4][4];
    #pragma unroll
    for (int mt = 0; mt < 2; ++mt)
        #pragma unroll
        for (int nt = 0; nt < 4; ++nt)
            #pragma unroll
            for (int e = 0; e < 4; ++e) acc[mt][nt][e] = 0.f;

    const int wm = (wid >> 2) << 5;
    const int wn = (wid & 3) << 5;
    const int lq = lid >> 3;
    const int lr = lid & 7;

    uint4 pa0, pa1, pl0, pl1, pb0, pb1, pq0, pq1;
    {
        pa0 = *(const uint4*)(Ah + (size_t)(m0 + r0_) * 768 + u0 * 8);
        pa1 = *(const uint4*)(Ah + (size_t)(m0 + r1_) * 768 + u1 * 8);
        pl0 = *(const uint4*)(Al + (size_t)(m0 + r0_) * 768 + u0 * 8);
        pl1 = *(const uint4*)(Al + (size_t)(m0 + r1_) * 768 + u1 * 8);
        pb0 = *(const uint4*)(Bh + (size_t)(n0 + r0_) * 768 + u0 * 8);
        pb1 = *(const uint4*)(Bh + (size_t)(n0 + r1_) * 768 + u1 * 8);
        pq0 = *(const uint4*)(Bl + (size_t)(n0 + r0_) * 768 + u0 * 8);
        pq1 = *(const uint4*)(Bl + (size_t)(n0 + r1_) * 768 + u1 * 8);
    }

    for (int c = 0; c < 12; ++c) {
        *(uint4*)(smem + SM_AH + so0) = pa0;  *(uint4*)(smem + SM_AH + so1) = pa1;
        *(uint4*)(smem + SM_AL + so0) = pl0;  *(uint4*)(smem + SM_AL + so1) = pl1;
        *(uint4*)(smem + SM_BH + so0) = pb0;  *(uint4*)(smem + SM_BH + so1) = pb1;
        *(uint4*)(smem + SM_BL + so0) = pq0;  *(uint4*)(smem + SM_BL + so1) = pq1;
        __syncthreads();

        if (c < 11) {
            const int ka = (c + 1) << 6;
            pa0 = *(const uint4*)(Ah + (size_t)(m0 + r0_) * 768 + ka + u0 * 8);
            pa1 = *(const uint4*)(Ah + (size_t)(m0 + r1_) * 768 + ka + u1 * 8);
            pl0 = *(const uint4*)(Al + (size_t)(m0 + r0_) * 768 + ka + u0 * 8);
            pl1 = *(const uint4*)(Al + (size_t)(m0 + r1_) * 768 + ka + u1 * 8);
            pb0 = *(const uint4*)(Bh + (size_t)(n0 + r0_) * 768 + ka + u0 * 8);
            pb1 = *(const uint4*)(Bh + (size_t)(n0 + r1_) * 768 + ka + u1 * 8);
            pq0 = *(const uint4*)(Bl + (size_t)(n0 + r0_) * 768 + ka + u0 * 8);
            pq1 = *(const uint4*)(Bl + (size_t)(n0 + r1_) * 768 + ka + u1 * 8);
        }

        #pragma unroll
        for (int ks = 0; ks < 4; ++ks) {
            uint32_t ah[2][4], alr[2][4];
            #pragma unroll
            for (int mt = 0; mt < 2; ++mt) {
                const int row = wm + mt * 16 + ((lq & 1) << 3) + lr;
                const int kc  = (ks << 4) + ((lq >> 1) << 3);
                const uint32_t off = (uint32_t)(row * 128 + ((kc * 2) ^ ((row & 7) << 4)));
                LDSM_X4(ah[mt][0], ah[mt][1], ah[mt][2], ah[mt][3], sb + SM_AH + off);
                LDSM_X4(alr[mt][0], alr[mt][1], alr[mt][2], alr[mt][3], sb + SM_AL + off);
            }
            uint32_t bh[4][2], bl[4][2];
            #pragma unroll
            for (int half = 0; half < 2; ++half) {
                const int nrow = wn + half * 16 + ((lq >> 1) << 3) + lr;
                const int kc   = (ks << 4) + ((lq & 1) << 3);
                const uint32_t off = (uint32_t)(nrow * 128 + ((kc * 2) ^ ((nrow & 7) << 4)));
                uint32_t t0, t1, t2, t3;
                LDSM_X4(t0, t1, t2, t3, sb + SM_BH + off);
                bh[half * 2][0] = t0;     bh[half * 2][1] = t1;
                bh[half * 2 + 1][0] = t2; bh[half * 2 + 1][1] = t3;
                LDSM_X4(t0, t1, t2, t3, sb + SM_BL + off);
                bl[half * 2][0] = t0;     bl[half * 2][1] = t1;
                bl[half * 2 + 1][0] = t2; bl[half * 2 + 1][1] = t3;
            }
            #pragma unroll
            for (int mt = 0; mt < 2; ++mt)
                #pragma unroll
                for (int nt = 0; nt < 4; ++nt) {
                    MMA_BF16(acc[mt][nt], ah[mt], bh[nt]);
                    MMA_BF16(acc[mt][nt], ah[mt], bl[nt]);
                    MMA_BF16(acc[mt][nt], alr[mt], bh[nt]);
                }
        }
        __syncthreads();
    }

    const int gID = lid >> 2;
    const int tc  = (lid & 3) << 1;
    const float* bs = (const float*)(smem + SM_BIAS);
    #pragma unroll
    for (int mt = 0; mt < 2; ++mt)
        #pragma unroll
        for (int nt = 0; nt < 4; ++nt) {
            const int colr = wn + nt * 8 + tc;
            const float b0 = bs[colr], b1 = bs[colr + 1];
            #pragma unroll
            for (int rh = 0; rh < 2; ++rh) {
                const int m = m0 + wm + mt * 16 + gID + rh * 8;
                float rx = acc[mt][nt][rh * 2 + 0] + b0;
                float ry = acc[mt][nt][rh * 2 + 1] + b1;
                if (SCATTER) {
                    const int b = m >> 11;
                    const int s = m & 2047;
                    const int head = (n0 + colr) >> 6;
                    const int dh   = (n0 + colr) & 63;
                    const size_t o = ((size_t)((b * 12 + head) << 11) + s) * 64 + dh;
                    __nv_bfloat16 hx = __float2bfloat16(rx);
                    __nv_bfloat16 hy = __float2bfloat16(ry);
                    __nv_bfloat16 lx = __float2bfloat16(rx - __bfloat162float(hx));
                    __nv_bfloat16 ly = __float2bfloat16(ry - __bfloat162float(hy));
                    *(__nv_bfloat162*)(dh_ + o) = __nv_bfloat162(hx, hy);
                    *(__nv_bfloat162*)(dl_ + o) = __nv_bfloat162(lx, ly);
                } else {
                    float2 r = make_float2(rx, ry);
                    *(float2*)&out[(size_t)m * 768 + n0 + colr] = r;
                }
            }
        }
}

// Fused Q/K/V projections: blockIdx.z = 0/1/2 selects input, weight, dest.
__global__ __launch_bounds__(512, 1) void gemm_qkv(const float* __restrict__ bq,
                                                   const float* __restrict__ bk,
                                                   const float* __restrict__ bv) {
    extern __shared__ __align__(1024) char smem[];
    const int z = blockIdx.z;
    const float* bias = (z == 0) ? bq : (z == 1) ? bk : bv;
    __nv_bfloat16* dh_ = (z == 0) ? g_qh : (z == 1) ? g_kh : g_vh;
    __nv_bfloat16* dl_ = (z == 0) ? g_ql : (z == 1) ? g_kl : g_vl;
    gemm_body<true>(g_inh[z], g_inl[z], g_wh[z], g_wl[z], bias,
                    dh_, dl_, nullptr, blockIdx.x << 7, blockIdx.y << 7, smem);
}

// Output projection: A = attention output split, W = Wo, fp32 out.
__global__ __launch_bounds__(512, 1) void gemm_out(const float* __restrict__ bo,
                                                   float* __restrict__ out) {
    extern __shared__ __align__(1024) char smem[];
    gemm_body<false>(g_atth, g_attl, g_wh[3], g_wl[3], bo,
                     nullptr, nullptr, out, blockIdx.x << 7, blockIdx.y << 7, smem);
}

// ---------------------------------------------------------------------------
// Flash attention on HMMA (bf16 hi/lo split, fp32 accum).
// CTA: 128 q-rows of one (b,h); 8 warps x 16 rows. Key tiles of 128,
// double-buffered K/V in smem via cp.async. Q fragments in registers.
// ---------------------------------------------------------------------------
#define FS_QH  0
#define FS_QL  16384
#define FS_KV  32768                 // + buf*65536 : KH, KL, VH, VL (16K each)
#define FS_TOT (32768 + 2 * 65536)   // 163840

__device__ __forceinline__ void fa_load_tile(uint32_t sb, int tid, size_t base,
                                             int t, int buf) {
    const uint32_t kb = FS_KV + (uint32_t)buf * 65536u;
    const int s0 = t << 7;
    #pragma unroll
    for (int r4 = 0; r4 < 4; ++r4) {
        const int u = r4 * 256 + tid;
        const int row = u >> 3, c16 = u & 7;
        const uint32_t so = (uint32_t)(row * 128 + ((c16 * 16) ^ ((row & 7) << 4)));
        const size_t g = base + (size_t)(s0 + row) * 64 + c16 * 8;
        CP_ASYNC16(sb + kb + so,         (const char*)(g_kh + g));
        CP_ASYNC16(sb + kb + 16384 + so, (const char*)(g_kl + g));
        CP_ASYNC16(sb + kb + 32768 + so, (const char*)(g_vh + g));
        CP_ASYNC16(sb + kb + 49152 + so, (const char*)(g_vl + g));
    }
}

__global__ __launch_bounds__(256, 1) void flash_mma(const float* __restrict__ mask)
{
    extern __shared__ __align__(1024) char smem[];
    const uint32_t sb = smem_u32(smem);
    const int tid = threadIdx.x;
    const int wid = tid >> 5;
    const int lid = tid & 31;
    const int lq  = lid >> 3;
    const int lr  = lid & 7;
    const int q0  = blockIdx.x << 7;
    const int bh  = blockIdx.y;
    const size_t base = (size_t)bh * SS * SDH;

    #pragma unroll
    for (int r4 = 0; r4 < 4; ++r4) {
        const int u = r4 * 256 + tid;
        const int row = u >> 3, c16 = u & 7;
        const uint32_t so = (uint32_t)(row * 128 + ((c16 * 16) ^ ((row & 7) << 4)));
        const size_t g = base + (size_t)(q0 + row) * 64 + c16 * 8;
        CP_ASYNC16(sb + FS_QH + so, (const char*)(g_qh + g));
        CP_ASYNC16(sb + FS_QL + so, (const char*)(g_ql + g));
    }
    fa_load_tile(sb, tid, base, 0, 0);
    CP_COMMIT();

    uint32_t qh[4][4], ql[4][4];
    float m_[2] = {-1e30f, -1e30f};
    float l_[2] = {0.f, 0.f};
    float o[8][4];
    #pragma unroll
    for (int d = 0; d < 8; ++d)
        #pragma unroll
        for (int e = 0; e < 4; ++e) o[d][e] = 0.f;

    for (int t = 0; t < 16; ++t) {
        CP_WAIT0();
        __syncthreads();

        if (t == 0) {
            #pragma unroll
            for (int ks = 0; ks < 4; ++ks) {
                const int row = (wid << 4) + ((lq & 1) << 3) + lr;
                const int kc  = (ks << 4) + ((lq >> 1) << 3);
                const uint32_t off = (uint32_t)(row * 128 + ((kc * 2) ^ ((row & 7) << 4)));
                LDSM_X4(qh[ks][0], qh[ks][1], qh[ks][2], qh[ks][3], sb + FS_QH + off);
                LDSM_X4(ql[ks][0], ql[ks][1], ql[ks][2], ql[ks][3], sb + FS_QL + off);
            }
        }
        if (t < 15) {
            fa_load_tile(sb, tid, base, t + 1, (t + 1) & 1);
            CP_COMMIT();
        }

        const uint32_t kb = FS_KV + (uint32_t)(t & 1) * 65536u;

        // ---- S = Q K^T (hi/lo split) ----
        float s_[16][4];
        #pragma unroll
        for (int nt = 0; nt < 16; ++nt)
            #pragma unroll
            for (int e = 0; e < 4; ++e) s_[nt][e] = 0.f;

        #pragma unroll
        for (int ks = 0; ks < 4; ++ks) {
            #pragma unroll
            for (int hf = 0; hf < 8; ++hf) {
                const int nrow = (hf << 4) + ((lq >> 1) << 3) + lr;
                const int kc   = (ks << 4) + ((lq & 1) << 3);
                const uint32_t off = (uint32_t)(nrow * 128 + ((kc * 2) ^ ((nrow & 7) << 4)));
                uint32_t a0, a1, a2, a3, b0, b1, b2, b3;
                LDSM_X4(a0, a1, a2, a3, sb + kb + off);            // K hi
                LDSM_X4(b0, b1, b2, b3, sb + kb + 16384 + off);    // K lo
                uint32_t kh0[2] = {a0, a1}, kh1[2] = {a2, a3};
                uint32_t kl0[2] = {b0, b1}, kl1[2] = {b2, b3};
                MMA_BF16(s_[hf * 2],     qh[ks], kh0);
                MMA_BF16(s_[hf * 2],     qh[ks], kl0);
                MMA_BF16(s_[hf * 2],     ql[ks], kh0);
                MMA_BF16(s_[hf * 2 + 1], qh[ks], kh1);
                MMA_BF16(s_[hf * 2 + 1], qh[ks], kl1);
                MMA_BF16(s_[hf * 2 + 1], ql[ks], kh1);
            }
        }

        // ---- mask + scale + online softmax ----
        const int rowA = q0 + (wid << 4) + (lid >> 2);
        const float* mrowA = mask + (size_t)rowA * SS + (t << 7) + ((lid & 3) << 1);
        const float* mrowB = mrowA + 8 * SS;
        float rmA = -1e30f, rmB = -1e30f;
        #pragma unroll
        for (int nt = 0; nt < 16; ++nt) {
            float2 ma = *(const float2*)(mrowA + nt * 8);
            float2 mb = *(const float2*)(mrowB + nt * 8);
            s_[nt][0] = (s_[nt][0] + ma.x) * 0.125f;
            s_[nt][1] = (s_[nt][1] + ma.y) * 0.125f;
            s_[nt][2] = (s_[nt][2] + mb.x) * 0.125f;
            s_[nt][3] = (s_[nt][3] + mb.y) * 0.125f;
            rmA = fmaxf(rmA, fmaxf(s_[nt][0], s_[nt][1]));
            rmB = fmaxf(rmB, fmaxf(s_[nt][2], s_[nt][3]));
        }
        rmA = fmaxf(rmA, __shfl_xor_sync(0xffffffffu, rmA, 1));
        rmA = fmaxf(rmA, __shfl_xor_sync(0xffffffffu, rmA, 2));
        rmB = fmaxf(rmB, __shfl_xor_sync(0xffffffffu, rmB, 1));
        rmB = fmaxf(rmB, __shfl_xor_sync(0xffffffffu, rmB, 2));
        const float mA = fmaxf(m_[0], rmA), mB = fmaxf(m_[1], rmB);
        const float aA = __expf(m_[0] - mA), aB = __expf(m_[1] - mB);
        m_[0] = mA; m_[1] = mB;

        float sA = 0.f, sB = 0.f;
        #pragma unroll
        for (int nt = 0; nt < 16; ++nt) {
            s_[nt][0] = __expf(s_[nt][0] - mA);
            s_[nt][1] = __expf(s_[nt][1] - mA);
            s_[nt][2] = __expf(s_[nt][2] - mB);
            s_[nt][3] = __expf(s_[nt][3] - mB);
            sA += s_[nt][0] + s_[nt][1];
            sB += s_[nt][2] + s_[nt][3];
        }
        sA += __shfl_xor_sync(0xffffffffu, sA, 1);
        sA += __shfl_xor_sync(0xffffffffu, sA, 2);
        sB += __shfl_xor_sync(0xffffffffu, sB, 1);
        sB += __shfl_xor_sync(0xffffffffu, sB, 2);
        l_[0] = l_[0] * aA + sA;
        l_[1] = l_[1] * aB + sB;

        #pragma unroll
        for (int d = 0; d < 8; ++d) {
            o[d][0] *= aA; o[d][1] *= aA;
            o[d][2] *= aB; o[d][3] *= aB;
        }

        // ---- O += P V (hi/lo split, V via ldmatrix.trans) ----
        #pragma unroll
        for (int ks = 0; ks < 8; ++ks) {
            const float x0 = s_[2 * ks][0], x1 = s_[2 * ks][1];
            const float x2 = s_[2 * ks][2], x3 = s_[2 * ks][3];
            const float y0 = s_[2 * ks + 1][0], y1 = s_[2 * ks + 1][1];
            const float y2 = s_[2 * ks + 1][2], y3 = s_[2 * ks + 1][3];
            __nv_bfloat16 hx0 = __float2bfloat16(x0), hx1 = __float2bfloat16(x1);
            __nv_bfloat16 hx2 = __float2bfloat16(x2), hx3 = __float2bfloat16(x3);
            __nv_bfloat16 hy0 = __float2bfloat16(y0), hy1 = __float2bfloat16(y1);
            __nv_bfloat16 hy2 = __float2bfloat16(y2), hy3 = __float2bfloat16(y3);
            uint32_t ph[4], pl[4];
            ph[0] = bpack(hx0, hx1);  ph[1] = bpack(hx2, hx3);
            ph[2] = bpack(hy0, hy1);  ph[3] = bpack(hy2, hy3);
            pl[0] = bpack(__float2bfloat16(x0 - __bfloat162float(hx0)),
                          __float2bfloat16(x1 - __bfloat162float(hx1)));
            pl[1] = bpack(__float2bfloat16(x2 - __bfloat162float(hx2)),
                          __float2bfloat16(x3 - __bfloat162float(hx3)));
            pl[2] = bpack(__float2bfloat16(y0 - __bfloat162float(hy0)),
                          __float2bfloat16(y1 - __bfloat162float(hy1)));
            pl[3] = bpack(__float2bfloat16(y2 - __bfloat162float(hy2)),
                          __float2bfloat16(y3 - __bfloat162float(hy3)));

            #pragma unroll
            for (int dp = 0; dp < 4; ++dp) {
                const int j = (ks << 4) + ((lq & 1) << 3) + lr;
                const int d = (dp << 4) + ((lq >> 1) << 3);
                const uint32_t off = (uint32_t)(j * 128 + ((d * 2) ^ ((j & 7) << 4)));
                uint32_t v0, v1, v2, v3, w0, w1, w2, w3;
                LDSM_X4_T(v0, v1, v2, v3, sb + kb + 32768 + off);   // V hi
                LDSM_X4_T(w0, w1, w2, w3, sb + kb + 49152 + off);   // V lo
                uint32_t vh0[2] = {v0, v1}, vh1[2] = {v2, v3};
                uint32_t vl0[2] = {w0, w1}, vl1[2] = {w2, w3};
                MMA_BF16(o[dp * 2],     ph, vh0);
                MMA_BF16(o[dp * 2],     ph, vl0);
                MMA_BF16(o[dp * 2],     pl, vh0);
                MMA_BF16(o[dp * 2 + 1], ph, vh1);
                MMA_BF16(o[dp * 2 + 1], ph, vl1);
                MMA_BF16(o[dp * 2 + 1], pl, vh1);
            }
        }
    }

    // ---- epilogue: normalize, bf16 hi/lo split to g_atth/g_attl ----
    const int b = bh / 12;
    const int h = bh % 12;
    const float invA = 1.f / l_[0];
    const float invB = 1.f / l_[1];
    const int sA_ = q0 + (wid << 4) + (lid >> 2);
    const int sB_ = sA_ + 8;
    #pragma unroll
    for (int dp = 0; dp < 8; ++dp) {
        const int d = dp * 8 + ((lid & 3) << 1);
        const size_t oa = ((size_t)(b * SS + sA_)) * SD + h * 64 + d;
        const size_t ob = ((size_t)(b * SS + sB_)) * SD + h * 64 + d;
        const float xa0 = o[dp][0] * invA, xa1 = o[dp][1] * invA;
        const float xb0 = o[dp][2] * invB, xb1 = o[dp][3] * invB;
        __nv_bfloat16 ha0 = __float2bfloat16(xa0), ha1 = __float2bfloat16(xa1);
        __nv_bfloat16 hb0 = __float2bfloat16(xb0), hb1 = __float2bfloat16(xb1);
        *(__nv_bfloat162*)(g_atth + oa) = __nv_bfloat162(ha0, ha1);
        *(__nv_bfloat162*)(g_atth + ob) = __nv_bfloat162(hb0, hb1);
        *(__nv_bfloat162*)(g_attl + oa) =
            __nv_bfloat162(__float2bfloat16(xa0 - __bfloat162float(ha0)),
                           __float2bfloat16(xa1 - __bfloat162float(ha1)));
        *(__nv_bfloat162*)(g_attl + ob) =
            __nv_bfloat162(__float2bfloat16(xb0 - __bfloat162float(hb0)),
                           __float2bfloat16(xb1 - __bfloat162float(hb1)));
    }
}

// ---------------------------------------------------------------------------
extern "C" void kernel_launch(void* const* d_in, const int* in_sizes, int n_in,
                              void* d_out, int out_size)
{
    const float* q    = (const float*)d_in[0];
    const float* k    = (const float*)d_in[1];
    const float* v    = (const float*)d_in[2];
    const float* mask = (const float*)d_in[3];
    const float* Wq   = (const float*)d_in[4];
    const float* bq   = (const float*)d_in[5];
    const float* Wk   = (const float*)d_in[6];
    const float* bk   = (const float*)d_in[7];
    const float* Wv   = (const float*)d_in[8];
    const float* bv   = (const float*)d_in[9];
    const float* Wo   = (const float*)d_in[10];
    const float* bo   = (const float*)d_in[11];
    float* out = (float*)d_out;

    (void)in_sizes; (void)n_in; (void)out_size;

    cudaFuncSetAttribute(gemm_qkv, cudaFuncAttributeMaxDynamicSharedMemorySize, SM_TOT);
    cudaFuncSetAttribute(gemm_out, cudaFuncAttributeMaxDynamicSharedMemorySize, SM_TOT);
    cudaFuncSetAttribute(flash_mma, cudaFuncAttributeMaxDynamicSharedMemorySize, FS_TOT);

    // launches 1-3: input splits (kept separate so flash_mma is launch #6 for ncu)
    split_in<<<3072, 256>>>(q, 0);
    split_in<<<3072, 256>>>(k, 1);
    split_in<<<3072, 256>>>(v, 2);
    // launch 4: all weight splits
    split_w<<<dim3(576, 4), 256>>>(Wq, Wk, Wv, Wo);

    // launch 5: fused QKV projections (576 CTAs = 3.9 waves vs 3 x 1.3)
    gemm_qkv<<<dim3(32, 6, 3), 512, SM_TOT>>>(bq, bk, bv);
    // launch 6: flash attention (profiled)
    flash_mma<<<dim3(SS / 128, SB * SH), 256, FS_TOT>>>(mask);
    // launch 7: output projection
    gemm_out<<<dim3(32, 6), 512, SM_TOT>>>(bo, out);
}